// round 2
// baseline (speedup 1.0000x reference)
#include <cuda_runtime.h>
#include <math.h>

// ---------------- problem constants ----------------
#define BATCH   32
#define CIN     256
#define COUT    64
#define HW      1024
#define NE      1024
#define EDIM    64
#define NROWS   32768
#define ZLEN    (BATCH*COUT*HW)   // 2097152
#define TILES   8
#define CODE_TILE 128
#define ES_STRIDE4 17             // 17 float4 = 68 floats per code row (bank-friendly, 16B aligned)

// output layout (concat, float32): z_q | loss | sampled | min_idx
#define ZQ_OFF   0
#define LOSS_OFF ((size_t)ZLEN)
#define SAMP_OFF ((size_t)ZLEN + 1)
#define MIDX_OFF ((size_t)ZLEN + 1 + NROWS)

// ---------------- device scratch ----------------
__device__ __align__(16) float g_z[ZLEN];
__device__ int   g_idx[NROWS];
__device__ float g_se[NE];           // sum(emb*emb, axis=1), replicated-order
__device__ float g_loss_part[1024];
__device__ float g_contrastive;

// Replicated XLA-CPU reduce order guess: VF=4, IC=2, fused fmla,
// faddp-adjacent horizontal: acc0 over elems 8t+{0..3}, acc1 over 8t+{4..7},
// L = acc0+acc1 (per lane), result = (L0+L1)+(L2+L3).
__device__ __forceinline__ float sumsq64(const float4* v4 /*16 float4*/) {
    float a0=0.f,a1=0.f,a2=0.f,a3=0.f, b0=0.f,b1=0.f,b2=0.f,b3=0.f;
    #pragma unroll
    for (int t = 0; t < 8; t++) {
        float4 x = v4[2*t];
        a0 = __fmaf_rn(x.x, x.x, a0); a1 = __fmaf_rn(x.y, x.y, a1);
        a2 = __fmaf_rn(x.z, x.z, a2); a3 = __fmaf_rn(x.w, x.w, a3);
        float4 y = v4[2*t+1];
        b0 = __fmaf_rn(y.x, y.x, b0); b1 = __fmaf_rn(y.y, y.y, b1);
        b2 = __fmaf_rn(y.z, y.z, b2); b3 = __fmaf_rn(y.w, y.w, b3);
    }
    float L0 = a0 + b0, L1 = a1 + b1, L2 = a2 + b2, L3 = a3 + b3;
    return (L0 + L1) + (L2 + L3);
}

// ============================================================
// K0: Se (codebook squared norms, replicated order) + contrastive
// ============================================================
__global__ void k_norms(const float* __restrict__ emb) {
    __shared__ float inv_norm[NE];
    __shared__ float s_part[4][EDIM];
    __shared__ float s_sq[EDIM];
    int tid = threadIdx.x;   // 256

    for (int i = tid; i < NE; i += 256) {
        const float4* e4 = (const float4*)(emb + (size_t)i * EDIM);
        float sq = sumsq64(e4);
        g_se[i] = sq;
        inv_norm[i] = 1.0f / sqrtf(sq);
    }
    __syncthreads();

    int k = tid & 63, part = tid >> 6;
    float s = 0.f;
    int i0 = part * 256;
    for (int i = i0; i < i0 + 256; i++)
        s += emb[(size_t)i * EDIM + k] * inv_norm[i];
    s_part[part][k] = s;
    __syncthreads();

    if (tid < EDIM) {
        float v = ((s_part[0][tid] + s_part[1][tid]) +
                   (s_part[2][tid] + s_part[3][tid]));
        s_sq[tid] = v * v;
    }
    __syncthreads();
    if (tid == 0) {
        float c = 0.f;
        for (int j = 0; j < EDIM; j++) c += s_sq[j];
        g_contrastive = c / ((float)NE * (float)NE);
    }
}

// ============================================================
// K1: 1x1 conv. Bitwise emulation of Eigen gemm + bias add:
// per output: single FMA chain, c ascending, start 0, bias added last.
// ============================================================
__global__ void k_conv(const float* __restrict__ zin,
                       const float* __restrict__ w,
                       const float* __restrict__ bias) {
    extern __shared__ float sm[];
    float* wsT = sm;               // [256][64]
    float* bs  = sm + CIN * COUT;
    int tid = threadIdx.x;         // 128

    for (int i = tid; i < COUT * CIN; i += 128) {
        int o = i >> 8, c = i & 255;
        wsT[c * COUT + o] = w[i];
    }
    if (tid < COUT) bs[tid] = bias[tid];
    __syncthreads();

    int b = blockIdx.x >> 3;
    int p = ((blockIdx.x & 7) << 7) + tid;
    const float* zp = zin + (size_t)b * CIN * HW + p;

    float acc[COUT];
    #pragma unroll
    for (int o = 0; o < COUT; o++) acc[o] = 0.0f;

    for (int c = 0; c < CIN; c++) {
        float zv = zp[(size_t)c * HW];
        const float4* w4 = (const float4*)(wsT + c * COUT);
        #pragma unroll
        for (int o4 = 0; o4 < 16; o4++) {
            float4 wv = w4[o4];
            acc[o4*4+0] = __fmaf_rn(zv, wv.x, acc[o4*4+0]);
            acc[o4*4+1] = __fmaf_rn(zv, wv.y, acc[o4*4+1]);
            acc[o4*4+2] = __fmaf_rn(zv, wv.z, acc[o4*4+2]);
            acc[o4*4+3] = __fmaf_rn(zv, wv.w, acc[o4*4+3]);
        }
    }
    float* zo = g_z + (size_t)b * COUT * HW + p;
    #pragma unroll
    for (int o = 0; o < COUT; o++) zo[(size_t)o * HW] = acc[o] + bs[o];
}

// ============================================================
// K2: argmin over codebook, bitwise-replicated distance:
//   d_j = fl( fl(Sz + Se_j) - 2*dot_j ),   dot_j = in-order 64-term FMA chain
// 8 threads per row scan disjoint code subsets (ascending), lexicographic merge.
// ============================================================
__global__ void __launch_bounds__(256, 2) k_argmin(const float* __restrict__ emb,
                                                   float* __restrict__ out) {
    __shared__ __align__(16) float es[CODE_TILE * ES_STRIDE4 * 4];   // 34816 B
    __shared__ float se_s[CODE_TILE];
    __shared__ float red[256];

    int tid = threadIdx.x;          // 256
    int s   = tid & 7;              // sub-lane within row
    int row = blockIdx.x * 32 + (tid >> 3);

    float4 zr4[16];
    {
        const float4* z4 = (const float4*)(g_z + (size_t)row * EDIM);
        #pragma unroll
        for (int k = 0; k < 16; k++) zr4[k] = z4[k];
    }
    float Sz = sumsq64(zr4);

    float best = 3.4e38f;
    int bi = 0;

    const float4* emb4 = (const float4*)emb;
    float4* es4 = (float4*)es;

    for (int t = 0; t < TILES; t++) {
        __syncthreads();
        #pragma unroll
        for (int idx = tid; idx < CODE_TILE * 16; idx += 256) {
            int j = idx >> 4, k4 = idx & 15;
            es4[j * ES_STRIDE4 + k4] = emb4[(size_t)(t * CODE_TILE + j) * 16 + k4];
        }
        if (tid < CODE_TILE) se_s[tid] = g_se[t * CODE_TILE + tid];
        __syncthreads();

        #pragma unroll
        for (int i4 = 0; i4 < 16; i4 += 4) {
            // codes j_c = (i4+c)*8 + s, c=0..3 (ascending global index)
            const float4* e0 = es4 + ((i4+0)*8 + s) * ES_STRIDE4;
            const float4* e1 = es4 + ((i4+1)*8 + s) * ES_STRIDE4;
            const float4* e2 = es4 + ((i4+2)*8 + s) * ES_STRIDE4;
            const float4* e3 = es4 + ((i4+3)*8 + s) * ES_STRIDE4;
            float d0 = 0.f, d1 = 0.f, d2 = 0.f, d3 = 0.f;
            #pragma unroll
            for (int k = 0; k < 16; k++) {
                float4 zv = zr4[k];
                float4 a = e0[k];
                d0 = __fmaf_rn(zv.x, a.x, d0); d0 = __fmaf_rn(zv.y, a.y, d0);
                d0 = __fmaf_rn(zv.z, a.z, d0); d0 = __fmaf_rn(zv.w, a.w, d0);
                float4 b = e1[k];
                d1 = __fmaf_rn(zv.x, b.x, d1); d1 = __fmaf_rn(zv.y, b.y, d1);
                d1 = __fmaf_rn(zv.z, b.z, d1); d1 = __fmaf_rn(zv.w, b.w, d1);
                float4 c = e2[k];
                d2 = __fmaf_rn(zv.x, c.x, d2); d2 = __fmaf_rn(zv.y, c.y, d2);
                d2 = __fmaf_rn(zv.z, c.z, d2); d2 = __fmaf_rn(zv.w, c.w, d2);
                float4 e = e3[k];
                d3 = __fmaf_rn(zv.x, e.x, d3); d3 = __fmaf_rn(zv.y, e.y, d3);
                d3 = __fmaf_rn(zv.z, e.z, d3); d3 = __fmaf_rn(zv.w, e.w, d3);
            }
            #pragma unroll
            for (int c = 0; c < 4; c++) {
                int jl = (i4 + c) * 8 + s;
                float dotv = (c==0)?d0:(c==1)?d1:(c==2)?d2:d3;
                float t1 = Sz + se_s[jl];                  // fl(Sz + Se)
                float dv = __fmaf_rn(-2.0f, dotv, t1);     // fl(t1 - 2*dot), 2*dot exact
                int gidx = t * CODE_TILE + jl;
                if (dv < best) { best = dv; bi = gidx; }   // ascending scan -> first min
            }
        }
    }

    // lexicographic merge across the 8 sub-lanes of this row
    unsigned m = 0xffffffffu;
    #pragma unroll
    for (int off = 4; off > 0; off >>= 1) {
        float ob = __shfl_down_sync(m, best, off, 8);
        int   oi = __shfl_down_sync(m, bi,   off, 8);
        if (ob < best || (ob == best && oi < bi)) { best = ob; bi = oi; }
    }
    bi = __shfl_sync(m, bi, 0, 8);   // broadcast winner within group of 8
    if (s == 0) g_idx[row] = bi;

    // epilogue: z_q_st = fl(z + fl(e - z)), loss partial (e - z)^2
    const float4* eb = (const float4*)(emb + (size_t)bi * EDIM) + s * 2;
    float4* outp = (float4*)(out + ZQ_OFF + (size_t)row * EDIM) + s * 2;
    float lacc = 0.f;
    #pragma unroll
    for (int q = 0; q < 2; q++) {
        float4 e = eb[q];
        float4 z = zr4[s * 2 + q];
        float dx = e.x - z.x, dy = e.y - z.y, dz = e.z - z.z, dw = e.w - z.w;
        float4 o;
        o.x = z.x + dx; o.y = z.y + dy; o.z = z.z + dz; o.w = z.w + dw;
        outp[q] = o;
        lacc += dx*dx + dy*dy + dz*dz + dw*dw;
    }
    red[tid] = lacc;
    __syncthreads();
    #pragma unroll
    for (int st = 128; st > 0; st >>= 1) {
        if (tid < st) red[tid] += red[tid + st];
        __syncthreads();
    }
    if (tid == 0) g_loss_part[blockIdx.x] = red[0];
}

// ============================================================
// K3: zero sampled + write min_idx; K4: scatter; K5: loss
// ============================================================
__global__ void k_misc(float* __restrict__ out) {
    int t = blockIdx.x * 256 + threadIdx.x;
    out[SAMP_OFF + t] = 0.0f;
    out[MIDX_OFF + t] = (float)g_idx[t];
}

__global__ void k_scatter(float* __restrict__ out) {
    int t = blockIdx.x * 256 + threadIdx.x;
    out[SAMP_OFF + g_idx[t]] = 1.0f;
}

__global__ void k_loss(float* __restrict__ out) {
    if (threadIdx.x == 0 && blockIdx.x == 0) {
        double sum = 0.0;
        for (int i = 0; i < 1024; i++) sum += (double)g_loss_part[i];
        out[LOSS_OFF] = (float)(1.25 * (sum / (double)ZLEN)) + g_contrastive;
    }
}

// ============================================================
extern "C" void kernel_launch(void* const* d_in, const int* in_sizes, int n_in,
                              void* d_out, int out_size) {
    const float* z_    = (const float*)d_in[0];
    const float* convw = (const float*)d_in[1];
    const float* convb = (const float*)d_in[2];
    const float* emb   = (const float*)d_in[3];
    float* out = (float*)d_out;

    cudaFuncSetAttribute(k_conv, cudaFuncAttributeMaxDynamicSharedMemorySize,
                         (CIN * COUT + COUT) * (int)sizeof(float));

    k_norms<<<1, 256>>>(emb);
    k_conv<<<256, 128, (CIN * COUT + COUT) * sizeof(float)>>>(z_, convw, convb);
    k_argmin<<<1024, 256>>>(emb, out);
    k_misc<<<128, 256>>>(out);
    k_scatter<<<128, 256>>>(out);
    k_loss<<<1, 32>>>(out);
}

// round 3
// speedup vs baseline: 1.2993x; 1.2993x over previous
#include <cuda_runtime.h>
#include <math.h>

// ---------------- problem constants ----------------
#define BATCH   32
#define CIN     256
#define COUT    64
#define HW      1024
#define NE      1024
#define EDIM    64
#define NROWS   32768
#define ZLEN    (BATCH*COUT*HW)   // 2097152
#define TILES   8
#define CODE_TILE 128
#define ES_STRIDE4 17             // float4 stride per code row: 68 floats -> bank offset 4/code

// output layout (concat, float32): z_q | loss | sampled | min_idx
#define ZQ_OFF   0
#define LOSS_OFF ((size_t)ZLEN)
#define SAMP_OFF ((size_t)ZLEN + 1)
#define MIDX_OFF ((size_t)ZLEN + 1 + NROWS)

// ---------------- device scratch ----------------
__device__ __align__(16) float g_z[ZLEN];
__device__ int   g_idx[NROWS];
__device__ float g_se[NE];             // sum(emb*emb, axis=1), replicated rounding order
__device__ float g_loss_part[1024];
__device__ float g_s_part[32 * EDIM];  // per-block partial of sum_i e_i/||e_i||

// Replicated XLA-CPU reduce order: VF=4, IC=2, fmla, faddp-adjacent horizontal.
// ONLY use with true memory pointers (gmem) — never a register array.
__device__ __forceinline__ float sumsq64_g(const float4* __restrict__ v4) {
    float a0=0.f,a1=0.f,a2=0.f,a3=0.f, b0=0.f,b1=0.f,b2=0.f,b3=0.f;
    #pragma unroll
    for (int t = 0; t < 8; t++) {
        float4 x = v4[2*t];
        a0 = __fmaf_rn(x.x, x.x, a0); a1 = __fmaf_rn(x.y, x.y, a1);
        a2 = __fmaf_rn(x.z, x.z, a2); a3 = __fmaf_rn(x.w, x.w, a3);
        float4 y = v4[2*t+1];
        b0 = __fmaf_rn(y.x, y.x, b0); b1 = __fmaf_rn(y.y, y.y, b1);
        b2 = __fmaf_rn(y.z, y.z, b2); b3 = __fmaf_rn(y.w, y.w, b3);
    }
    float L0 = a0 + b0, L1 = a1 + b1, L2 = a2 + b2, L3 = a3 + b3;
    return (L0 + L1) + (L2 + L3);
}

// ============================================================
// K0: Se (codebook squared norms) + per-block normalized-sum partials
// 32 blocks x 256 threads; block b owns codes [b*32, b*32+32)
// ============================================================
__global__ void k_norms(const float* __restrict__ emb) {
    __shared__ float inv_n[32];
    __shared__ float sq[4][EDIM];
    int b = blockIdx.x, tid = threadIdx.x;

    if (tid < 32) {
        int i = b * 32 + tid;
        float v = sumsq64_g((const float4*)(emb + (size_t)i * EDIM));
        g_se[i] = v;
        inv_n[tid] = 1.0f / sqrtf(v);
    }
    __syncthreads();

    int k = tid & 63, q = tid >> 6;
    float sacc = 0.f;
    #pragma unroll
    for (int i = 0; i < 8; i++) {
        int code = q * 8 + i;
        sacc += emb[(size_t)(b * 32 + code) * EDIM + k] * inv_n[code];
    }
    sq[q][k] = sacc;
    __syncthreads();
    if (tid < EDIM)
        g_s_part[b * EDIM + tid] = (sq[0][tid] + sq[1][tid]) + (sq[2][tid] + sq[3][tid]);
}

// ============================================================
// K1: 1x1 conv. Bitwise Eigen order: single FMA chain per output,
// c ascending from 0, bias added after the chain.
// ============================================================
__global__ void k_conv(const float* __restrict__ zin,
                       const float* __restrict__ w,
                       const float* __restrict__ bias) {
    extern __shared__ float sm[];
    float* wsT = sm;               // [256][64]
    float* bs  = sm + CIN * COUT;
    int tid = threadIdx.x;         // 128

    for (int i = tid; i < COUT * CIN; i += 128) {
        int o = i >> 8, c = i & 255;
        wsT[c * COUT + o] = w[i];
    }
    if (tid < COUT) bs[tid] = bias[tid];
    __syncthreads();

    int b = blockIdx.x >> 3;
    int p = ((blockIdx.x & 7) << 7) + tid;
    const float* zp = zin + (size_t)b * CIN * HW + p;

    float acc[COUT];
    #pragma unroll
    for (int o = 0; o < COUT; o++) acc[o] = 0.0f;

    for (int c = 0; c < CIN; c++) {
        float zv = zp[(size_t)c * HW];
        const float4* w4 = (const float4*)(wsT + c * COUT);
        #pragma unroll
        for (int o4 = 0; o4 < 16; o4++) {
            float4 wv = w4[o4];
            acc[o4*4+0] = __fmaf_rn(zv, wv.x, acc[o4*4+0]);
            acc[o4*4+1] = __fmaf_rn(zv, wv.y, acc[o4*4+1]);
            acc[o4*4+2] = __fmaf_rn(zv, wv.z, acc[o4*4+2]);
            acc[o4*4+3] = __fmaf_rn(zv, wv.w, acc[o4*4+3]);
        }
    }
    float* zo = g_z + (size_t)b * COUT * HW + p;
    #pragma unroll
    for (int o = 0; o < COUT; o++) zo[(size_t)o * HW] = acc[o] + bs[o];
}

// ============================================================
// K2: fused distance+argmin+z_q+loss-partial+min_idx+sampled-zero.
// d_j = fl( fl(Sz + Se_j) - 2*dot_j ), dot = in-order 64-term FMA chain.
// 8 sublanes per row scan interleaved codes; lexicographic merge.
// NOTE: zr[] is only ever indexed by compile-time constants and its
// address never escapes -> stays in registers.
// ============================================================
__global__ void __launch_bounds__(256, 2) k_argmin(const float* __restrict__ emb,
                                                   float* __restrict__ out) {
    __shared__ __align__(16) float4 es4[CODE_TILE * ES_STRIDE4];  // 34816 B
    __shared__ float se_s[CODE_TILE];
    __shared__ float red[256];

    int tid = threadIdx.x;          // 256
    int s   = tid & 7;              // sub-lane within row
    int row = blockIdx.x * 32 + (tid >> 3);

    float4 zr[16];
    {
        const float4* z4 = (const float4*)(g_z + (size_t)row * EDIM);
        #pragma unroll
        for (int k = 0; k < 16; k++) zr[k] = z4[k];
    }

    // Sz inline, replicated order (acc0: elems 8t+{0..3}, acc1: 8t+{4..7})
    float Sz;
    {
        float a0=0.f,a1=0.f,a2=0.f,a3=0.f, b0=0.f,b1=0.f,b2=0.f,b3=0.f;
        #pragma unroll
        for (int t = 0; t < 8; t++) {
            float4 x = zr[2*t];
            a0 = __fmaf_rn(x.x, x.x, a0); a1 = __fmaf_rn(x.y, x.y, a1);
            a2 = __fmaf_rn(x.z, x.z, a2); a3 = __fmaf_rn(x.w, x.w, a3);
            float4 y = zr[2*t+1];
            b0 = __fmaf_rn(y.x, y.x, b0); b1 = __fmaf_rn(y.y, y.y, b1);
            b2 = __fmaf_rn(y.z, y.z, b2); b3 = __fmaf_rn(y.w, y.w, b3);
        }
        float L0 = a0 + b0, L1 = a1 + b1, L2 = a2 + b2, L3 = a3 + b3;
        Sz = (L0 + L1) + (L2 + L3);
    }

    float best = 3.4e38f;
    int bi = 0;
    const float4* emb4 = (const float4*)emb;

    for (int t = 0; t < TILES; t++) {
        __syncthreads();
        #pragma unroll
        for (int idx = tid; idx < CODE_TILE * 16; idx += 256) {
            int j = idx >> 4, k4 = idx & 15;
            es4[j * ES_STRIDE4 + k4] = emb4[(size_t)(t * CODE_TILE + j) * 16 + k4];
        }
        if (tid < CODE_TILE) se_s[tid] = g_se[t * CODE_TILE + tid];
        __syncthreads();

        #pragma unroll
        for (int i4 = 0; i4 < 16; i4 += 4) {
            const float4* e0 = es4 + ((i4+0)*8 + s) * ES_STRIDE4;
            const float4* e1 = es4 + ((i4+1)*8 + s) * ES_STRIDE4;
            const float4* e2 = es4 + ((i4+2)*8 + s) * ES_STRIDE4;
            const float4* e3 = es4 + ((i4+3)*8 + s) * ES_STRIDE4;
            float d0 = 0.f, d1 = 0.f, d2 = 0.f, d3 = 0.f;
            #pragma unroll
            for (int k = 0; k < 16; k++) {
                float4 zv = zr[k];
                float4 a = e0[k];
                d0 = __fmaf_rn(zv.x, a.x, d0); d0 = __fmaf_rn(zv.y, a.y, d0);
                d0 = __fmaf_rn(zv.z, a.z, d0); d0 = __fmaf_rn(zv.w, a.w, d0);
                float4 b = e1[k];
                d1 = __fmaf_rn(zv.x, b.x, d1); d1 = __fmaf_rn(zv.y, b.y, d1);
                d1 = __fmaf_rn(zv.z, b.z, d1); d1 = __fmaf_rn(zv.w, b.w, d1);
                float4 c = e2[k];
                d2 = __fmaf_rn(zv.x, c.x, d2); d2 = __fmaf_rn(zv.y, c.y, d2);
                d2 = __fmaf_rn(zv.z, c.z, d2); d2 = __fmaf_rn(zv.w, c.w, d2);
                float4 e = e3[k];
                d3 = __fmaf_rn(zv.x, e.x, d3); d3 = __fmaf_rn(zv.y, e.y, d3);
                d3 = __fmaf_rn(zv.z, e.z, d3); d3 = __fmaf_rn(zv.w, e.w, d3);
            }
            #pragma unroll
            for (int c = 0; c < 4; c++) {
                int jl = (i4 + c) * 8 + s;
                float dotv = (c==0)?d0:(c==1)?d1:(c==2)?d2:d3;
                float t1 = Sz + se_s[jl];
                float dv = __fmaf_rn(-2.0f, dotv, t1);
                int gidx = t * CODE_TILE + jl;
                if (dv < best) { best = dv; bi = gidx; }
            }
        }
    }

    // lexicographic merge across the 8 sub-lanes of this row
    unsigned m = 0xffffffffu;
    #pragma unroll
    for (int off = 4; off > 0; off >>= 1) {
        float ob = __shfl_down_sync(m, best, off, 8);
        int   oi = __shfl_down_sync(m, bi,   off, 8);
        if (ob < best || (ob == best && oi < bi)) { best = ob; bi = oi; }
    }
    bi = __shfl_sync(m, bi, 0, 8);
    if (s == 0) {
        g_idx[row] = bi;
        out[MIDX_OFF + row] = (float)bi;   // exact small int
        out[SAMP_OFF + row] = 0.0f;        // pre-zero sampled region
    }

    // epilogue: z_q_st = fl(z + fl(e - z)); loss partial (e - z)^2.
    // re-read z from gmem (L2-hot) to avoid dynamic indexing of zr[].
    const float4* eb = (const float4*)(emb + (size_t)bi * EDIM) + s * 2;
    const float4* zg = (const float4*)(g_z + (size_t)row * EDIM) + s * 2;
    float4* outp = (float4*)(out + ZQ_OFF + (size_t)row * EDIM) + s * 2;
    float lacc = 0.f;
    #pragma unroll
    for (int q = 0; q < 2; q++) {
        float4 e = eb[q];
        float4 z = zg[q];
        float dx = e.x - z.x, dy = e.y - z.y, dz = e.z - z.z, dw = e.w - z.w;
        float4 o;
        o.x = z.x + dx; o.y = z.y + dy; o.z = z.z + dz; o.w = z.w + dw;
        outp[q] = o;
        lacc += dx*dx + dy*dy + dz*dz + dw*dw;
    }
    red[tid] = lacc;
    __syncthreads();
    #pragma unroll
    for (int st = 128; st > 0; st >>= 1) {
        if (tid < st) red[tid] += red[tid + st];
        __syncthreads();
    }
    if (tid == 0) g_loss_part[blockIdx.x] = red[0];
}

// ============================================================
// K3: scatter ones into sampled; block 0 also finalizes the loss scalar
// ============================================================
__global__ void k_scatter(float* __restrict__ out) {
    int tid = threadIdx.x;
    int t = blockIdx.x * 256 + tid;
    out[SAMP_OFF + g_idx[t]] = 1.0f;

    if (blockIdx.x == 0) {
        __shared__ double rd[256];
        __shared__ float sv[EDIM];
        double a = 0.0;
        #pragma unroll
        for (int i = tid; i < 1024; i += 256) a += (double)g_loss_part[i];
        rd[tid] = a;
        if (tid < EDIM) {
            float v = 0.f;
            #pragma unroll
            for (int j = 0; j < 32; j++) v += g_s_part[j * EDIM + tid];
            sv[tid] = v * v;
        }
        __syncthreads();
        #pragma unroll
        for (int st = 128; st > 0; st >>= 1) {
            if (tid < st) rd[tid] += rd[tid + st];
            __syncthreads();
        }
        if (tid == 0) {
            float c = 0.f;
            for (int j = 0; j < EDIM; j++) c += sv[j];
            out[LOSS_OFF] = (float)(1.25 * (rd[0] / (double)ZLEN))
                          + c / ((float)NE * (float)NE);
        }
    }
}

// ============================================================
extern "C" void kernel_launch(void* const* d_in, const int* in_sizes, int n_in,
                              void* d_out, int out_size) {
    const float* z_    = (const float*)d_in[0];
    const float* convw = (const float*)d_in[1];
    const float* convb = (const float*)d_in[2];
    const float* emb   = (const float*)d_in[3];
    float* out = (float*)d_out;

    cudaFuncSetAttribute(k_conv, cudaFuncAttributeMaxDynamicSharedMemorySize,
                         (CIN * COUT + COUT) * (int)sizeof(float));

    k_norms<<<32, 256>>>(emb);
    k_conv<<<256, 128, (CIN * COUT + COUT) * sizeof(float)>>>(z_, convw, convb);
    k_argmin<<<1024, 256>>>(emb, out);
    k_scatter<<<128, 256>>>(out);
}

// round 4
// speedup vs baseline: 1.3825x; 1.0640x over previous
#include <cuda_runtime.h>
#include <math.h>

// ---------------- problem constants ----------------
#define BATCH   32
#define CIN     256
#define COUT    64
#define HW      1024
#define NE      1024
#define EDIM    64
#define NROWS   32768
#define ZLEN    (BATCH*COUT*HW)   // 2097152
#define TILES   8
#define CODE_TILE 128
#define PAIRS_PER_TILE 64
#define PAIR_STRIDE4 33           // 33 float4 = 132 floats per pair row

// output layout (concat, float32): z_q | loss | sampled | min_idx
#define ZQ_OFF   0
#define LOSS_OFF ((size_t)ZLEN)
#define SAMP_OFF ((size_t)ZLEN + 1)
#define MIDX_OFF ((size_t)ZLEN + 1 + NROWS)

// ---------------- device scratch ----------------
__device__ __align__(16) float g_z[ZLEN];
__device__ __align__(16) float g_embi[NE * EDIM];   // pair-interleaved codebook
__device__ int   g_idx[NROWS];
__device__ float g_se[NE];
__device__ float g_loss_part[1024];
__device__ float g_s_part[32 * EDIM];

// ---------------- packed f32x2 helpers (bit-exact per-lane fma.rn) ----------------
__device__ __forceinline__ unsigned long long dupf(float v) {
    unsigned long long r;
    asm("mov.b64 %0, {%1, %1};" : "=l"(r) : "r"(__float_as_uint(v)));
    return r;
}
__device__ __forceinline__ void fma2(unsigned long long& d,
                                     unsigned long long a, unsigned long long b) {
    asm("fma.rn.f32x2 %0, %1, %2, %0;" : "+l"(d) : "l"(a), "l"(b));
}
__device__ __forceinline__ void unpack2(float& lo, float& hi, unsigned long long v) {
    asm("mov.b64 {%0, %1}, %2;" : "=f"(lo), "=f"(hi) : "l"(v));
}

// Replicated XLA-CPU reduce order: VF=4, IC=2, fmla, faddp-adjacent horizontal.
__device__ __forceinline__ float sumsq64_g(const float4* __restrict__ v4) {
    float a0=0.f,a1=0.f,a2=0.f,a3=0.f, b0=0.f,b1=0.f,b2=0.f,b3=0.f;
    #pragma unroll
    for (int t = 0; t < 8; t++) {
        float4 x = v4[2*t];
        a0 = __fmaf_rn(x.x, x.x, a0); a1 = __fmaf_rn(x.y, x.y, a1);
        a2 = __fmaf_rn(x.z, x.z, a2); a3 = __fmaf_rn(x.w, x.w, a3);
        float4 y = v4[2*t+1];
        b0 = __fmaf_rn(y.x, y.x, b0); b1 = __fmaf_rn(y.y, y.y, b1);
        b2 = __fmaf_rn(y.z, y.z, b2); b3 = __fmaf_rn(y.w, y.w, b3);
    }
    float L0 = a0 + b0, L1 = a1 + b1, L2 = a2 + b2, L3 = a3 + b3;
    return (L0 + L1) + (L2 + L3);
}

// ============================================================
// K0: Se + contrastive partials (32 blocks x 256)
// ============================================================
__global__ void k_norms(const float* __restrict__ emb) {
    __shared__ float inv_n[32];
    __shared__ float sq[4][EDIM];
    int b = blockIdx.x, tid = threadIdx.x;

    if (tid < 32) {
        int i = b * 32 + tid;
        float v = sumsq64_g((const float4*)(emb + (size_t)i * EDIM));
        g_se[i] = v;
        inv_n[tid] = 1.0f / sqrtf(v);
    }
    __syncthreads();

    int k = tid & 63, q = tid >> 6;
    float sacc = 0.f;
    #pragma unroll
    for (int i = 0; i < 8; i++) {
        int code = q * 8 + i;
        sacc += emb[(size_t)(b * 32 + code) * EDIM + k] * inv_n[code];
    }
    sq[q][k] = sacc;
    __syncthreads();
    if (tid < EDIM)
        g_s_part[b * EDIM + tid] = (sq[0][tid] + sq[1][tid]) + (sq[2][tid] + sq[3][tid]);
}

// ============================================================
// K0b: interleave codebook into pair layout:
// out[((t*64 + q*8 + s)*64 + k)*2 + l] = emb[(t*128 + 16q + s + 8l)*64 + k]
// ============================================================
__global__ void k_prep(const float* __restrict__ emb) {
    int o = blockIdx.x * 256 + threadIdx.x;        // 0..65535
    int P = o >> 7, r = o & 127;
    int k = r >> 1, l = r & 1;
    int t = P >> 6, q = (P >> 3) & 7, s = P & 7;
    int j = t * 128 + 16 * q + s + 8 * l;
    g_embi[o] = emb[(size_t)j * EDIM + k];
}

// ============================================================
// K1: 1x1 conv with packed FMA2 on output pairs (o, o+1).
// Bitwise Eigen order: per output single FMA chain, c ascending, bias last.
// ============================================================
__global__ void __launch_bounds__(128) k_conv(const float* __restrict__ zin,
                                              const float* __restrict__ w,
                                              const float* __restrict__ bias) {
    extern __shared__ float sm[];
    float* wsT = sm;               // [256][64]
    float* bs  = sm + CIN * COUT;
    int tid = threadIdx.x;         // 128

    for (int i = tid; i < COUT * CIN; i += 128) {
        int o = i >> 8, c = i & 255;
        wsT[c * COUT + o] = w[i];
    }
    if (tid < COUT) bs[tid] = bias[tid];
    __syncthreads();

    int b = blockIdx.x >> 3;
    int p = ((blockIdx.x & 7) << 7) + tid;
    const float* zp = zin + (size_t)b * CIN * HW + p;

    unsigned long long acc2[32];   // output pairs (2pr, 2pr+1)
    #pragma unroll
    for (int pr = 0; pr < 32; pr++) acc2[pr] = 0ULL;

    float zn[8];
    #pragma unroll
    for (int i = 0; i < 8; i++) zn[i] = zp[(size_t)i * HW];

    for (int ch = 0; ch < 32; ch++) {
        float zc[8];
        #pragma unroll
        for (int i = 0; i < 8; i++) zc[i] = zn[i];
        if (ch < 31) {
            #pragma unroll
            for (int i = 0; i < 8; i++)
                zn[i] = zp[(size_t)((ch + 1) * 8 + i) * HW];
        }
        #pragma unroll
        for (int cc = 0; cc < 8; cc++) {
            int c = ch * 8 + cc;
            unsigned long long zz = dupf(zc[cc]);
            const ulonglong2* w2 = (const ulonglong2*)(wsT + c * COUT);
            #pragma unroll
            for (int u = 0; u < 16; u++) {
                ulonglong2 wp = w2[u];     // pairs 2u and 2u+1
                fma2(acc2[2*u],     zz, wp.x);
                fma2(acc2[2*u + 1], zz, wp.y);
            }
        }
    }

    float* zo = g_z + (size_t)b * COUT * HW + p;
    #pragma unroll
    for (int pr = 0; pr < 32; pr++) {
        float lo, hi;
        unpack2(lo, hi, acc2[pr]);
        zo[(size_t)(2*pr)   * HW] = lo + bs[2*pr];
        zo[(size_t)(2*pr+1) * HW] = hi + bs[2*pr+1];
    }
}

// ============================================================
// K2: fused distance+argmin, packed FMA2 on code pairs (16q+s, 16q+8+s).
// d_j = fl( fl(Sz + Se_j) - 2*dot_j ), dot = in-order 64-term chain per lane.
// ============================================================
__global__ void __launch_bounds__(256, 2) k_argmin(float* __restrict__ out,
                                                   const float* __restrict__ emb) {
    __shared__ __align__(16) float4 es4[PAIRS_PER_TILE * PAIR_STRIDE4];  // 33792 B
    __shared__ float se_s[CODE_TILE];
    __shared__ float red[256];

    int tid = threadIdx.x;
    int s   = tid & 7;
    int row = blockIdx.x * 32 + (tid >> 3);

    float4 zr[16];
    {
        const float4* z4 = (const float4*)(g_z + (size_t)row * EDIM);
        #pragma unroll
        for (int k = 0; k < 16; k++) zr[k] = z4[k];
    }

    float Sz;
    {
        float a0=0.f,a1=0.f,a2=0.f,a3=0.f, b0=0.f,b1=0.f,b2=0.f,b3=0.f;
        #pragma unroll
        for (int t = 0; t < 8; t++) {
            float4 x = zr[2*t];
            a0 = __fmaf_rn(x.x, x.x, a0); a1 = __fmaf_rn(x.y, x.y, a1);
            a2 = __fmaf_rn(x.z, x.z, a2); a3 = __fmaf_rn(x.w, x.w, a3);
            float4 y = zr[2*t+1];
            b0 = __fmaf_rn(y.x, y.x, b0); b1 = __fmaf_rn(y.y, y.y, b1);
            b2 = __fmaf_rn(y.z, y.z, b2); b3 = __fmaf_rn(y.w, y.w, b3);
        }
        float L0 = a0 + b0, L1 = a1 + b1, L2 = a2 + b2, L3 = a3 + b3;
        Sz = (L0 + L1) + (L2 + L3);
    }

    float best = 3.4e38f;
    int bi = 0;
    const float4* gsrc = (const float4*)g_embi;

    for (int t = 0; t < TILES; t++) {
        __syncthreads();
        const float4* src = gsrc + (size_t)t * 2048;
        #pragma unroll
        for (int i = 0; i < 8; i++) {
            int idx = tid + 256 * i;
            int pr = idx >> 5, wv = idx & 31;
            es4[pr * PAIR_STRIDE4 + wv] = src[idx];
        }
        if (tid < CODE_TILE) se_s[tid] = g_se[t * CODE_TILE + tid];
        __syncthreads();

        unsigned long long acc[8];
        #pragma unroll
        for (int q = 0; q < 8; q++) acc[q] = 0ULL;

        const ulonglong2* ebase = (const ulonglong2*)(es4 + s * PAIR_STRIDE4);
        #pragma unroll
        for (int k4 = 0; k4 < 16; k4++) {
            float4 zv = zr[k4];
            unsigned long long zx = dupf(zv.x), zy = dupf(zv.y),
                               zz = dupf(zv.z), zw = dupf(zv.w);
            #pragma unroll
            for (int q = 0; q < 8; q++) {
                const ulonglong2* ep = ebase + q * 8 * PAIR_STRIDE4;
                ulonglong2 e01 = ep[2 * k4];       // dims 4k4, 4k4+1
                ulonglong2 e23 = ep[2 * k4 + 1];   // dims 4k4+2, 4k4+3
                fma2(acc[q], zx, e01.x);
                fma2(acc[q], zy, e01.y);
                fma2(acc[q], zz, e23.x);
                fma2(acc[q], zw, e23.y);
            }
        }

        #pragma unroll
        for (int q = 0; q < 8; q++) {
            float dlo, dhi;
            unpack2(dlo, dhi, acc[q]);
            int jlo = 16 * q + s, jhi = jlo + 8;
            float t1 = Sz + se_s[jlo];
            float dv = __fmaf_rn(-2.0f, dlo, t1);
            if (dv < best) { best = dv; bi = t * CODE_TILE + jlo; }
            float t2 = Sz + se_s[jhi];
            float dw = __fmaf_rn(-2.0f, dhi, t2);
            if (dw < best) { best = dw; bi = t * CODE_TILE + jhi; }
        }
    }

    // lexicographic merge across the 8 sub-lanes of this row
    unsigned m = 0xffffffffu;
    #pragma unroll
    for (int off = 4; off > 0; off >>= 1) {
        float ob = __shfl_down_sync(m, best, off, 8);
        int   oi = __shfl_down_sync(m, bi,   off, 8);
        if (ob < best || (ob == best && oi < bi)) { best = ob; bi = oi; }
    }
    bi = __shfl_sync(m, bi, 0, 8);
    if (s == 0) {
        g_idx[row] = bi;
        out[MIDX_OFF + row] = (float)bi;
        out[SAMP_OFF + row] = 0.0f;
    }

    // epilogue: z_q_st = fl(z + fl(e - z)); loss partial (e - z)^2
    const float4* eb = (const float4*)(emb + (size_t)bi * EDIM) + s * 2;
    const float4* zg = (const float4*)(g_z + (size_t)row * EDIM) + s * 2;
    float4* outp = (float4*)(out + ZQ_OFF + (size_t)row * EDIM) + s * 2;
    float lacc = 0.f;
    #pragma unroll
    for (int q = 0; q < 2; q++) {
        float4 e = eb[q];
        float4 z = zg[q];
        float dx = e.x - z.x, dy = e.y - z.y, dz = e.z - z.z, dw = e.w - z.w;
        float4 o;
        o.x = z.x + dx; o.y = z.y + dy; o.z = z.z + dz; o.w = z.w + dw;
        outp[q] = o;
        lacc += dx*dx + dy*dy + dz*dz + dw*dw;
    }
    red[tid] = lacc;
    __syncthreads();
    #pragma unroll
    for (int st = 128; st > 0; st >>= 1) {
        if (tid < st) red[tid] += red[tid + st];
        __syncthreads();
    }
    if (tid == 0) g_loss_part[blockIdx.x] = red[0];
}

// ============================================================
// K3: scatter + loss finalize
// ============================================================
__global__ void k_scatter(float* __restrict__ out) {
    int tid = threadIdx.x;
    int t = blockIdx.x * 256 + tid;
    out[SAMP_OFF + g_idx[t]] = 1.0f;

    if (blockIdx.x == 0) {
        __shared__ double rd[256];
        __shared__ float sv[EDIM];
        double a = 0.0;
        #pragma unroll
        for (int i = tid; i < 1024; i += 256) a += (double)g_loss_part[i];
        rd[tid] = a;
        if (tid < EDIM) {
            float v = 0.f;
            #pragma unroll
            for (int j = 0; j < 32; j++) v += g_s_part[j * EDIM + tid];
            sv[tid] = v * v;
        }
        __syncthreads();
        #pragma unroll
        for (int st = 128; st > 0; st >>= 1) {
            if (tid < st) rd[tid] += rd[tid + st];
            __syncthreads();
        }
        if (tid == 0) {
            float c = 0.f;
            for (int j = 0; j < EDIM; j++) c += sv[j];
            out[LOSS_OFF] = (float)(1.25 * (rd[0] / (double)ZLEN))
                          + c / ((float)NE * (float)NE);
        }
    }
}

// ============================================================
extern "C" void kernel_launch(void* const* d_in, const int* in_sizes, int n_in,
                              void* d_out, int out_size) {
    const float* z_    = (const float*)d_in[0];
    const float* convw = (const float*)d_in[1];
    const float* convb = (const float*)d_in[2];
    const float* emb   = (const float*)d_in[3];
    float* out = (float*)d_out;

    cudaFuncSetAttribute(k_conv, cudaFuncAttributeMaxDynamicSharedMemorySize,
                         (CIN * COUT + COUT) * (int)sizeof(float));

    k_norms<<<32, 256>>>(emb);
    k_prep<<<256, 256>>>(emb);
    k_conv<<<256, 128, (CIN * COUT + COUT) * sizeof(float)>>>(z_, convw, convb);
    k_argmin<<<1024, 256>>>(out, emb);
    k_scatter<<<128, 256>>>(out);
}

// round 5
// speedup vs baseline: 3.0998x; 2.2422x over previous
#include <cuda_runtime.h>
#include <math.h>

// ---------------- problem constants ----------------
#define BATCH   32
#define CIN     256
#define COUT    64
#define HW      1024
#define NE      1024
#define EDIM    64
#define NROWS   32768
#define ZLEN    (BATCH*COUT*HW)   // 2097152
#define TILES   8
#define CODE_TILE 128

// output layout (concat, float32): z_q | loss | sampled | min_idx
#define ZQ_OFF   0
#define LOSS_OFF ((size_t)ZLEN)
#define SAMP_OFF ((size_t)ZLEN + 1)
#define MIDX_OFF ((size_t)ZLEN + 1 + NROWS)

// argmin smem layout (dynamic): zs4[128*17] | es4[64*33] | se[128] | red[256]
#define ZS_F4    (128 * 17)
#define ES_F4    (64 * 33)
#define SMEM_ARGMIN ((ZS_F4 + ES_F4) * 16 + 128 * 4 + 256 * 4)   // 70144 B

// ---------------- device scratch ----------------
__device__ __align__(16) float g_z[ZLEN];
__device__ __align__(16) float g_embi[NE * EDIM];   // pair-interleaved codebook
__device__ int   g_idx[NROWS];
__device__ float g_se[NE];
__device__ float g_sz[NROWS];
__device__ float g_loss_part[256];
__device__ float g_s_part[32 * EDIM];

// ---------------- packed f32x2 helpers (bit-exact per-lane fma.rn) ----------------
__device__ __forceinline__ unsigned long long dupf(float v) {
    unsigned long long r;
    asm("mov.b64 %0, {%1, %1};" : "=l"(r) : "r"(__float_as_uint(v)));
    return r;
}
__device__ __forceinline__ unsigned long long pack2(float a, float b) {
    unsigned long long r;
    asm("mov.b64 %0, {%1, %2};" : "=l"(r) : "r"(__float_as_uint(a)), "r"(__float_as_uint(b)));
    return r;
}
__device__ __forceinline__ void fma2(unsigned long long& d,
                                     unsigned long long a, unsigned long long b) {
    asm("fma.rn.f32x2 %0, %1, %2, %0;" : "+l"(d) : "l"(a), "l"(b));
}
__device__ __forceinline__ void unpack2(float& lo, float& hi, unsigned long long v) {
    asm("mov.b64 {%0, %1}, %2;" : "=f"(lo), "=f"(hi) : "l"(v));
}

// Replicated XLA-CPU reduce order: VF=4, IC=2, fmla, faddp-adjacent horizontal.
__device__ __forceinline__ float sumsq64_g(const float4* __restrict__ v4) {
    float a0=0.f,a1=0.f,a2=0.f,a3=0.f, b0=0.f,b1=0.f,b2=0.f,b3=0.f;
    #pragma unroll
    for (int t = 0; t < 8; t++) {
        float4 x = v4[2*t];
        a0 = __fmaf_rn(x.x, x.x, a0); a1 = __fmaf_rn(x.y, x.y, a1);
        a2 = __fmaf_rn(x.z, x.z, a2); a3 = __fmaf_rn(x.w, x.w, a3);
        float4 y = v4[2*t+1];
        b0 = __fmaf_rn(y.x, y.x, b0); b1 = __fmaf_rn(y.y, y.y, b1);
        b2 = __fmaf_rn(y.z, y.z, b2); b3 = __fmaf_rn(y.w, y.w, b3);
    }
    float L0 = a0 + b0, L1 = a1 + b1, L2 = a2 + b2, L3 = a3 + b3;
    return (L0 + L1) + (L2 + L3);
}

// ============================================================
// K0: Se + contrastive partials
// ============================================================
__global__ void k_norms(const float* __restrict__ emb) {
    __shared__ float inv_n[32];
    __shared__ float sq[4][EDIM];
    int b = blockIdx.x, tid = threadIdx.x;

    if (tid < 32) {
        int i = b * 32 + tid;
        float v = sumsq64_g((const float4*)(emb + (size_t)i * EDIM));
        g_se[i] = v;
        inv_n[tid] = 1.0f / sqrtf(v);
    }
    __syncthreads();

    int k = tid & 63, q = tid >> 6;
    float sacc = 0.f;
    #pragma unroll
    for (int i = 0; i < 8; i++) {
        int code = q * 8 + i;
        sacc += emb[(size_t)(b * 32 + code) * EDIM + k] * inv_n[code];
    }
    sq[q][k] = sacc;
    __syncthreads();
    if (tid < EDIM)
        g_s_part[b * EDIM + tid] = (sq[0][tid] + sq[1][tid]) + (sq[2][tid] + sq[3][tid]);
}

// ============================================================
// K0b: interleave codebook into pair layout
// g_embi[((t*64 + q*8 + s)*64 + k)*2 + l] = emb[(t*128 + 16q + s + 8l)*64 + k]
// ============================================================
__global__ void k_prep(const float* __restrict__ emb) {
    int o = blockIdx.x * 256 + threadIdx.x;
    int P = o >> 7, r = o & 127;
    int k = r >> 1, l = r & 1;
    int t = P >> 6, q = (P >> 3) & 7, s = P & 7;
    int j = t * 128 + 16 * q + s + 8 * l;
    g_embi[o] = emb[(size_t)j * EDIM + k];
}

// ============================================================
// K1: 1x1 conv, register-tiled: 16 outputs (8 FMA2 pairs) x 4 pixels per thread.
// Weights pair-interleaved in smem -> 4 broadcast LDS.128 per channel for
// 32 FMA2. Bitwise Eigen order: per output single chain, c ascending, bias last.
// grid 256 = b(32) x half(2) x og(4); 128 threads.
// ============================================================
__global__ void __launch_bounds__(128) k_conv(const float* __restrict__ zin,
                                              const float* __restrict__ w,
                                              const float* __restrict__ bias) {
    __shared__ unsigned long long ws[CIN * 8];   // [c][pair u] packed (w[2u][c], w[2u+1][c])
    __shared__ float bs[16];

    int tid = threadIdx.x;
    int blk = blockIdx.x;
    int b = blk >> 3, half = (blk >> 2) & 1, og = blk & 3;
    int obase = og * 16;

    for (int m = tid; m < CIN * 8; m += 128) {
        int c = m >> 3, u = m & 7;
        const float* wp = w + (size_t)(obase + 2 * u) * CIN + c;
        ws[m] = pack2(wp[0], wp[CIN]);
    }
    if (tid < 16) bs[tid] = bias[obase + tid];
    __syncthreads();

    int p0 = half * 512 + tid;                   // pixels p0 + 128j
    const float* zp = zin + (size_t)b * CIN * HW + p0;

    unsigned long long acc[8][4];                // [pair u][pixel j]
    #pragma unroll
    for (int u = 0; u < 8; u++)
        #pragma unroll
        for (int j = 0; j < 4; j++) acc[u][j] = 0ULL;

    float zn[4][8];
    #pragma unroll
    for (int j = 0; j < 4; j++)
        #pragma unroll
        for (int i = 0; i < 8; i++)
            zn[j][i] = zp[(size_t)i * HW + 128 * j];

    const ulonglong2* ws2 = (const ulonglong2*)ws;
    for (int ch = 0; ch < 32; ch++) {
        float zc[4][8];
        #pragma unroll
        for (int j = 0; j < 4; j++)
            #pragma unroll
            for (int i = 0; i < 8; i++) zc[j][i] = zn[j][i];
        if (ch < 31) {
            #pragma unroll
            for (int j = 0; j < 4; j++)
                #pragma unroll
                for (int i = 0; i < 8; i++)
                    zn[j][i] = zp[(size_t)((ch + 1) * 8 + i) * HW + 128 * j];
        }
        #pragma unroll
        for (int cc = 0; cc < 8; cc++) {
            int c = ch * 8 + cc;
            unsigned long long zz[4];
            #pragma unroll
            for (int j = 0; j < 4; j++) zz[j] = dupf(zc[j][cc]);
            const ulonglong2* wrow = ws2 + c * 4;
            #pragma unroll
            for (int uu = 0; uu < 4; uu++) {
                ulonglong2 wp = wrow[uu];
                #pragma unroll
                for (int j = 0; j < 4; j++) {
                    fma2(acc[2*uu][j],     zz[j], wp.x);
                    fma2(acc[2*uu + 1][j], zz[j], wp.y);
                }
            }
        }
    }

    float* zo = g_z + (size_t)b * COUT * HW;
    #pragma unroll
    for (int u = 0; u < 8; u++) {
        int o = obase + 2 * u;
        #pragma unroll
        for (int j = 0; j < 4; j++) {
            float lo, hi;
            unpack2(lo, hi, acc[u][j]);
            zo[(size_t)o * HW + p0 + 128 * j]       = lo + bs[2*u];
            zo[(size_t)(o + 1) * HW + p0 + 128 * j] = hi + bs[2*u + 1];
        }
    }
}

// ============================================================
// K1b: Sz per row (replicated chain order), read g_z
// ============================================================
__global__ void k_sz(void) {
    int r = blockIdx.x * 256 + threadIdx.x;
    g_sz[r] = sumsq64_g((const float4*)(g_z + (size_t)r * EDIM));
}

// ============================================================
// K2: fused distance+argmin, 4 rows x 8 code-pairs per thread.
// Block: 128 rows; thread (g = tid>>3, s = tid&7) handles rows g+32i.
// d_j = fl( fl(Sz + Se_j) - 2*dot_j ), dot = in-order 64-term chain per lane.
// ============================================================
__global__ void __launch_bounds__(256, 2) k_argmin(float* __restrict__ out,
                                                   const float* __restrict__ emb) {
    extern __shared__ __align__(16) char smem[];
    float4* zs4 = (float4*)smem;                       // [128][17]
    float4* es4 = zs4 + ZS_F4;                         // [64 pairs][33]
    float*  se_s = (float*)(es4 + ES_F4);              // [128]
    float*  red  = se_s + 128;                         // [256]

    int tid = threadIdx.x;
    int s   = tid & 7;
    int g   = tid >> 3;
    int row0 = blockIdx.x * 128;

    // load block's 128 z rows into smem (pad stride 17 float4)
    {
        const float4* zsrc = (const float4*)(g_z + (size_t)row0 * EDIM);
        #pragma unroll
        for (int j = 0; j < 8; j++) {
            int idx = tid + 256 * j;               // 0..2047
            int r = idx >> 4, k4 = idx & 15;
            zs4[r * 17 + k4] = zsrc[idx];
        }
    }

    float Sz[4];
    #pragma unroll
    for (int i = 0; i < 4; i++) Sz[i] = g_sz[row0 + g + 32 * i];

    float best[4];
    int   bi[4];
    #pragma unroll
    for (int i = 0; i < 4; i++) { best[i] = 3.4e38f; bi[i] = 0; }

    const float4* gsrc = (const float4*)g_embi;

    for (int t = 0; t < TILES; t++) {
        __syncthreads();
        const float4* src = gsrc + (size_t)t * 2048;
        #pragma unroll
        for (int j = 0; j < 8; j++) {
            int idx = tid + 256 * j;
            int pr = idx >> 5, wv = idx & 31;
            es4[pr * 33 + wv] = src[idx];
        }
        if (tid < CODE_TILE) se_s[tid] = g_se[t * CODE_TILE + tid];
        __syncthreads();

        unsigned long long acc[8][4];
        #pragma unroll
        for (int q = 0; q < 8; q++)
            #pragma unroll
            for (int i = 0; i < 4; i++) acc[q][i] = 0ULL;

        const ulonglong2* ebase = (const ulonglong2*)(es4 + s * 33);

        #pragma unroll
        for (int k4 = 0; k4 < 16; k4++) {
            float4 z0 = zs4[(g +  0) * 17 + k4];
            float4 z1 = zs4[(g + 32) * 17 + k4];
            float4 z2 = zs4[(g + 64) * 17 + k4];
            float4 z3 = zs4[(g + 96) * 17 + k4];

            // half A: dims 4k4, 4k4+1
            {
                unsigned long long zx0 = dupf(z0.x), zx1 = dupf(z1.x),
                                   zx2 = dupf(z2.x), zx3 = dupf(z3.x);
                unsigned long long zy0 = dupf(z0.y), zy1 = dupf(z1.y),
                                   zy2 = dupf(z2.y), zy3 = dupf(z3.y);
                #pragma unroll
                for (int q = 0; q < 8; q++) {
                    ulonglong2 e01 = ebase[q * 8 * 33 + 2 * k4];
                    fma2(acc[q][0], zx0, e01.x); fma2(acc[q][0], zy0, e01.y);
                    fma2(acc[q][1], zx1, e01.x); fma2(acc[q][1], zy1, e01.y);
                    fma2(acc[q][2], zx2, e01.x); fma2(acc[q][2], zy2, e01.y);
                    fma2(acc[q][3], zx3, e01.x); fma2(acc[q][3], zy3, e01.y);
                }
            }
            // half B: dims 4k4+2, 4k4+3
            {
                unsigned long long zx0 = dupf(z0.z), zx1 = dupf(z1.z),
                                   zx2 = dupf(z2.z), zx3 = dupf(z3.z);
                unsigned long long zy0 = dupf(z0.w), zy1 = dupf(z1.w),
                                   zy2 = dupf(z2.w), zy3 = dupf(z3.w);
                #pragma unroll
                for (int q = 0; q < 8; q++) {
                    ulonglong2 e23 = ebase[q * 8 * 33 + 2 * k4 + 1];
                    fma2(acc[q][0], zx0, e23.x); fma2(acc[q][0], zy0, e23.y);
                    fma2(acc[q][1], zx1, e23.x); fma2(acc[q][1], zy1, e23.y);
                    fma2(acc[q][2], zx2, e23.x); fma2(acc[q][2], zy2, e23.y);
                    fma2(acc[q][3], zx3, e23.x); fma2(acc[q][3], zy3, e23.y);
                }
            }
        }

        #pragma unroll
        for (int q = 0; q < 8; q++) {
            int jlo = 16 * q + s, jhi = jlo + 8;
            float selo = se_s[jlo], sehi = se_s[jhi];
            #pragma unroll
            for (int i = 0; i < 4; i++) {
                float dlo, dhi;
                unpack2(dlo, dhi, acc[q][i]);
                float t1 = Sz[i] + selo;
                float dv = __fmaf_rn(-2.0f, dlo, t1);
                if (dv < best[i]) { best[i] = dv; bi[i] = t * CODE_TILE + jlo; }
                float t2 = Sz[i] + sehi;
                float dw = __fmaf_rn(-2.0f, dhi, t2);
                if (dw < best[i]) { best[i] = dw; bi[i] = t * CODE_TILE + jhi; }
            }
        }
    }

    // lexicographic merge across the 8 sub-lanes (per row)
    unsigned m = 0xffffffffu;
    #pragma unroll
    for (int i = 0; i < 4; i++) {
        float bv = best[i]; int bj = bi[i];
        #pragma unroll
        for (int off = 4; off > 0; off >>= 1) {
            float ob = __shfl_down_sync(m, bv, off, 8);
            int   oi = __shfl_down_sync(m, bj, off, 8);
            if (ob < bv || (ob == bv && oi < bj)) { bv = ob; bj = oi; }
        }
        bj = __shfl_sync(m, bj, 0, 8);
        bi[i] = bj;
    }

    // epilogue: per row i: idx/sampled/min_idx, z_q_st = fl(z + fl(e - z)), loss
    float lacc = 0.f;
    #pragma unroll
    for (int i = 0; i < 4; i++) {
        int rl = g + 32 * i;
        int row = row0 + rl;
        if (s == 0) {
            g_idx[row] = bi[i];
            out[MIDX_OFF + row] = (float)bi[i];
            out[SAMP_OFF + row] = 0.0f;
        }
        const float4* eb = (const float4*)(emb + (size_t)bi[i] * EDIM) + s * 2;
        float4* outp = (float4*)(out + ZQ_OFF + (size_t)row * EDIM) + s * 2;
        #pragma unroll
        for (int q = 0; q < 2; q++) {
            float4 e = eb[q];
            float4 z = zs4[rl * 17 + s * 2 + q];
            float dx = e.x - z.x, dy = e.y - z.y, dz = e.z - z.z, dw = e.w - z.w;
            float4 o;
            o.x = z.x + dx; o.y = z.y + dy; o.z = z.z + dz; o.w = z.w + dw;
            outp[q] = o;
            lacc += dx*dx + dy*dy + dz*dz + dw*dw;
        }
    }
    red[tid] = lacc;
    __syncthreads();
    #pragma unroll
    for (int st = 128; st > 0; st >>= 1) {
        if (tid < st) red[tid] += red[tid + st];
        __syncthreads();
    }
    if (tid == 0) g_loss_part[blockIdx.x] = red[0];
}

// ============================================================
// K3: scatter + loss finalize (256 loss parts now)
// ============================================================
__global__ void k_scatter(float* __restrict__ out) {
    int tid = threadIdx.x;
    int t = blockIdx.x * 256 + tid;
    out[SAMP_OFF + g_idx[t]] = 1.0f;

    if (blockIdx.x == 0) {
        __shared__ double rd[256];
        __shared__ float sv[EDIM];
        rd[tid] = (double)g_loss_part[tid];
        if (tid < EDIM) {
            float v = 0.f;
            #pragma unroll
            for (int j = 0; j < 32; j++) v += g_s_part[j * EDIM + tid];
            sv[tid] = v * v;
        }
        __syncthreads();
        #pragma unroll
        for (int st = 128; st > 0; st >>= 1) {
            if (tid < st) rd[tid] += rd[tid + st];
            __syncthreads();
        }
        if (tid == 0) {
            float c = 0.f;
            for (int j = 0; j < EDIM; j++) c += sv[j];
            out[LOSS_OFF] = (float)(1.25 * (rd[0] / (double)ZLEN))
                          + c / ((float)NE * (float)NE);
        }
    }
}

// ============================================================
extern "C" void kernel_launch(void* const* d_in, const int* in_sizes, int n_in,
                              void* d_out, int out_size) {
    const float* z_    = (const float*)d_in[0];
    const float* convw = (const float*)d_in[1];
    const float* convb = (const float*)d_in[2];
    const float* emb   = (const float*)d_in[3];
    float* out = (float*)d_out;

    cudaFuncSetAttribute(k_argmin, cudaFuncAttributeMaxDynamicSharedMemorySize,
                         SMEM_ARGMIN);

    k_norms<<<32, 256>>>(emb);
    k_prep<<<256, 256>>>(emb);
    k_conv<<<256, 128>>>(z_, convw, convb);
    k_sz<<<128, 256>>>();
    k_argmin<<<256, 256, SMEM_ARGMIN>>>(out, emb);
    k_scatter<<<128, 256>>>(out);
}